// round 12
// baseline (speedup 1.0000x reference)
#include <cuda_runtime.h>
#include <cuda_fp16.h>

// Problem constants
#define NW 16384   // words
#define WL 16      // word length
#define D  300     // hidden dim
#define DP 320     // padded channel count (zeros in [300,320))
#define NL 128     // letters
#define KS 3       // conv taps

// Encode config: slices 0/1 = 128 ch (2 words/warp), slice 2 = 64 ch
// (4 words/warp). 1024 threads/CTA, 2 CTA/SM -> 64 warps/SM (SM max).
#define WPB 32
#define ENC_THREADS 1024
#define B0 118
#define B1 118
#define B2 60
#define ENC_BLOCKS (B0 + B1 + B2)           // 296 = 2 CTA/SM * 148 SMs
#define ENC_SMEM (KS * NL * 128 * 2)        // 96 KB

// Fused prep: blocks [0,32) pack words (32*512 = 16384), blocks [32,112)
// build P (80 blocks x 4 channels = 320). 112 blocks = ONE wave @ 1 CTA/SM.
#define PACKB 32
#define PREP_BLOCKS 112
#define PREP_THREADS 512
#define ES_STRIDE 308   // floats; conflict-free LDS.128 (77 quads, gcd(77,8)=1)
#define PREP_SMEM ((NL * ES_STRIDE + 4 * KS * 304) * 4)  // 172288 B

// Device scratch
__device__ __half g_Ph[KS][NL][DP];  // per-letter conv partials (fp16, padded)
                                     // k=1 tap has conv bias folded in
__device__ uint4  g_wpk[NW];         // packed letters: 16 u8 per word

// packed-f32x2 FMA (FFMA2) — only reachable via PTX
__device__ __forceinline__ void fma2(unsigned long long& d,
                                     unsigned long long a, unsigned long long b) {
    asm("fma.rn.f32x2 %0, %1, %2, %0;" : "+l"(d) : "l"(a), "l"(b));
}
__device__ __forceinline__ float2 unpack2(unsigned long long x) {
    float2 f;
    asm("mov.b64 {%0, %1}, %2;" : "=f"(f.x), "=f"(f.y) : "l"(x));
    return f;
}

// ---------------------------------------------------------------------------
// Kernel 1 (fused prep, ONE wave):
//  blocks [0,32):  pack each word's 16 letters into one uint4 of u8.
//  blocks [32,112): P[k][v][o] = sum_i emb[v,i] * w[o,i,k] (+bias into k=1).
//    Whole emb staged in smem (coalesced); w reads are warp-uniform
//    broadcasts; FFMA2 pairs the fp32 math.
// ---------------------------------------------------------------------------
__global__ __launch_bounds__(PREP_THREADS) void prep_kernel(const int* __restrict__ words,
                                                            const float* __restrict__ emb,
                                                            const float* __restrict__ w,
                                                            const float* __restrict__ bias) {
    if (blockIdx.x < PACKB) {
        const int n = blockIdx.x * PREP_THREADS + threadIdx.x;
        unsigned r0 = 0, r1 = 0, r2 = 0, r3 = 0;
#pragma unroll
        for (int l = 0; l < 4; ++l)  r0 |= ((unsigned)words[l * NW + n] & 0xFF) << (l * 8);
#pragma unroll
        for (int l = 4; l < 8; ++l)  r1 |= ((unsigned)words[l * NW + n] & 0xFF) << ((l - 4) * 8);
#pragma unroll
        for (int l = 8; l < 12; ++l) r2 |= ((unsigned)words[l * NW + n] & 0xFF) << ((l - 8) * 8);
#pragma unroll
        for (int l = 12; l < 16; ++l) r3 |= ((unsigned)words[l * NW + n] & 0xFF) << ((l - 12) * 8);
        g_wpk[n] = make_uint4(r0, r1, r2, r3);
        return;
    }

    // ---- P branch: 4 output channels per block ----
    extern __shared__ float sm[];
    float* es = sm;                       // [128][ES_STRIDE]
    float* ws = sm + NL * ES_STRIDE;      // [4][KS][304]

    const int ob = (blockIdx.x - PACKB) * 4;
    const int j  = threadIdx.x >> 7;      // 0..3 (channel within block)
    const int v  = threadIdx.x & 127;     // letter
    const int o  = ob + j;

    // Stage emb [128][300] -> es (coalesced float4 reads & writes)
    const float4* e4 = (const float4*)emb;
    for (int idx = threadIdx.x; idx < NL * (D / 4); idx += PREP_THREADS) {
        int vv = idx / (D / 4), c = idx % (D / 4);
        *(float4*)&es[vv * ES_STRIDE + c * 4] = e4[idx];
    }
    // Stage w rows de-interleaved: ws[jj][k][i]
    for (int t = threadIdx.x; t < 4 * D * KS; t += PREP_THREADS) {
        int jj = t / (D * KS), r = t % (D * KS);
        int oo = ob + jj;
        ws[(jj * KS + r % 3) * 304 + r / 3] = (oo < D) ? w[oo * D * KS + r] : 0.f;
    }
    __syncthreads();

    typedef unsigned long long u64;
    u64 a0l = 0, a0h = 0, a1l = 0, a1h = 0, a2l = 0, a2h = 0;
    const float* ev  = es + v * ES_STRIDE;
    const float* w0p = ws + (j * KS + 0) * 304;
    const float* w1p = ws + (j * KS + 1) * 304;
    const float* w2p = ws + (j * KS + 2) * 304;
#pragma unroll 5
    for (int i = 0; i < D; i += 4) {
        ulonglong2 e2 = *(const ulonglong2*)(ev + i);
        ulonglong2 w0 = *(const ulonglong2*)(w0p + i);
        ulonglong2 w1 = *(const ulonglong2*)(w1p + i);
        ulonglong2 w2 = *(const ulonglong2*)(w2p + i);
        fma2(a0l, e2.x, w0.x); fma2(a0h, e2.y, w0.y);
        fma2(a1l, e2.x, w1.x); fma2(a1h, e2.y, w1.y);
        fma2(a2l, e2.x, w2.x); fma2(a2h, e2.y, w2.y);
    }
    float2 p0 = unpack2(a0l), q0 = unpack2(a0h);
    float2 p1 = unpack2(a1l), q1 = unpack2(a1h);
    float2 p2 = unpack2(a2l), q2 = unpack2(a2h);
    float a0 = (p0.x + p0.y) + (q0.x + q0.y);
    float a1 = (p1.x + p1.y) + (q1.x + q1.y);
    float a2 = (p2.x + p2.y) + (q2.x + q2.y);

    bool real = (o < D);
    float bv = real ? bias[o] : 0.f;
    g_Ph[0][v][o] = __float2half(real ? a0 : 0.f);
    g_Ph[1][v][o] = __float2half(real ? (a1 + bv) : 0.f);  // bias folded into k=1
    g_Ph[2][v][o] = __float2half(real ? a2 : 0.f);
}

// ---------------------------------------------------------------------------
// Kernel 2: encode. 296 blocks (118/118/60), 1024 thr, 2 CTA/SM ->
// 64 warps/SM (SM max). No letter prefetch — 16 warps/SMSP hide the
// once-per-iteration L2 letter load. Slices 0/1 (128 ch): 2 words/warp.
// Slice 2 (64 ch): 4 words/warp. Per position: 3 conflict-free LDS.128 +
// half2 adds + half2 running max. Bias already in the table.
// ---------------------------------------------------------------------------
#define GETL(l) ((lw[(l) >> 2] >> (((l) & 3) * 8)) & 0xFF)

#define INNER_BODY(loidx)                                                        \
    half2 m0 = NEGI, m1 = NEGI, m2 = NEGI, m3 = NEGI;                            \
    _Pragma("unroll")                                                            \
    for (int l = 0; l < WL; ++l) {                                               \
        uint4 a = Pv[(NL + GETL(l)) * 16 + (loidx)];                             \
        half2 h0 = *(half2*)&a.x, h1 = *(half2*)&a.y;                            \
        half2 h2 = *(half2*)&a.z, h3 = *(half2*)&a.w;                            \
        if (l > 0) {                                                             \
            uint4 q = Pv[GETL(l - 1) * 16 + (loidx)];                            \
            h0 = __hadd2(h0, *(half2*)&q.x); h1 = __hadd2(h1, *(half2*)&q.y);    \
            h2 = __hadd2(h2, *(half2*)&q.z); h3 = __hadd2(h3, *(half2*)&q.w);    \
        }                                                                        \
        if (l < WL - 1) {                                                        \
            uint4 q = Pv[(2 * NL + GETL(l + 1)) * 16 + (loidx)];                 \
            h0 = __hadd2(h0, *(half2*)&q.x); h1 = __hadd2(h1, *(half2*)&q.y);    \
            h2 = __hadd2(h2, *(half2*)&q.z); h3 = __hadd2(h3, *(half2*)&q.w);    \
        }                                                                        \
        m0 = __hmax2(m0, h0); m1 = __hmax2(m1, h1);                              \
        m2 = __hmax2(m2, h2); m3 = __hmax2(m3, h3);                              \
    }

__global__ __launch_bounds__(ENC_THREADS, 2) void encode_kernel(float* __restrict__ out) {
    extern __shared__ uint4 Pv[];  // [KS*NL rows][16 uint4]

    int b = blockIdx.x;
    int slice, lb, nb;
    if (b < B0)           { slice = 0; lb = b;           nb = B0; }
    else if (b < B0 + B1) { slice = 1; lb = b - B0;      nb = B1; }
    else                  { slice = 2; lb = b - B0 - B1; nb = B2; }
    const int c0 = slice * 128;
    const int nchunk = (slice == 2) ? 8 : 16;  // valid uint4 chunks per row

    const uint4* gP = (const uint4*)g_Ph;  // row stride DP/8 = 40 uint4
    for (int idx = threadIdx.x; idx < KS * NL * nchunk; idx += ENC_THREADS) {
        int r = idx / nchunk, c = idx % nchunk;
        Pv[r * 16 + c] = gP[r * (DP / 8) + slice * 16 + c];
    }
    __syncthreads();

    const int lane  = threadIdx.x & 31;
    const int wid   = threadIdx.x >> 5;
    const int wsl   = lb * WPB + wid;
    const int nwarp = nb * WPB;

    const __half NH = __ushort_as_half((unsigned short)0xFC00);  // -inf
    const half2 NEGI = __halves2half2(NH, NH);

    if (slice < 2) {
        // ---- 128-ch slice: 2 words per warp (16-lane halves) ----
        const int lo   = lane & 15;
        const int half = lane >> 4;
        const int ch   = c0 + lo * 8;

        for (int p = wsl; p < NW / 2; p += nwarp) {
            const int gw = 2 * p + half;
            uint4 pk = g_wpk[gw];
            unsigned lw[4] = {pk.x, pk.y, pk.z, pk.w};

            INNER_BODY(lo)

            float2 f0 = __half22float2(m0), f1 = __half22float2(m1);
            float2 f2 = __half22float2(m2), f3 = __half22float2(m3);
            float* op = out + (size_t)gw * D + ch;
            float4 r;
            r.x = fmaxf(f0.x, 0.f); r.y = fmaxf(f0.y, 0.f);
            r.z = fmaxf(f1.x, 0.f); r.w = fmaxf(f1.y, 0.f);
            *(float4*)op = r;
            r.x = fmaxf(f2.x, 0.f); r.y = fmaxf(f2.y, 0.f);
            r.z = fmaxf(f3.x, 0.f); r.w = fmaxf(f3.y, 0.f);
            *(float4*)(op + 4) = r;
        }
    } else {
        // ---- 64-ch slice (channels 256..299 real): 4 words per warp ----
        const int lo8 = lane & 7;
        const int g   = lane >> 3;
        const int ch  = c0 + lo8 * 8;  // 256..312

        for (int p = wsl; p < NW / 4; p += nwarp) {
            const int gw = 4 * p + g;
            uint4 pk = g_wpk[gw];
            unsigned lw[4] = {pk.x, pk.y, pk.z, pk.w};

            INNER_BODY(lo8)

            float2 f0 = __half22float2(m0), f1 = __half22float2(m1);
            float2 f2 = __half22float2(m2), f3 = __half22float2(m3);
            float* op = out + (size_t)gw * D + ch;
            if (ch < D) {
                float4 r;
                r.x = fmaxf(f0.x, 0.f); r.y = fmaxf(f0.y, 0.f);
                r.z = fmaxf(f1.x, 0.f); r.w = fmaxf(f1.y, 0.f);
                *(float4*)op = r;
            }
            if (ch + 4 < D) {
                float4 r;
                r.x = fmaxf(f2.x, 0.f); r.y = fmaxf(f2.y, 0.f);
                r.z = fmaxf(f3.x, 0.f); r.w = fmaxf(f3.y, 0.f);
                *(float4*)(op + 4) = r;
            }
        }
    }
}

// ---------------------------------------------------------------------------
// Launch. Inputs: words(int32), emb(f32), conv_w(f32), conv_b(f32). Out f32.
// ---------------------------------------------------------------------------
extern "C" void kernel_launch(void* const* d_in, const int* in_sizes, int n_in,
                              void* d_out, int out_size) {
    const int*   words = (const int*)d_in[0];
    const float* emb   = (const float*)d_in[1];
    const float* w     = (const float*)d_in[2];
    const float* b     = (const float*)d_in[3];
    float*       out   = (float*)d_out;

    cudaFuncSetAttribute(prep_kernel,
                         cudaFuncAttributeMaxDynamicSharedMemorySize, PREP_SMEM);
    prep_kernel<<<PREP_BLOCKS, PREP_THREADS, PREP_SMEM>>>(words, emb, w, b);

    cudaFuncSetAttribute(encode_kernel,
                         cudaFuncAttributeMaxDynamicSharedMemorySize, ENC_SMEM);
    encode_kernel<<<ENC_BLOCKS, ENC_THREADS, ENC_SMEM>>>(out);
}

// round 13
// speedup vs baseline: 1.0562x; 1.0562x over previous
#include <cuda_runtime.h>
#include <cuda_fp16.h>

// Problem constants
#define NW 16384   // words
#define WL 16      // word length
#define D  300     // hidden dim
#define DP 320     // padded channel count (zeros in [300,320))
#define NL 128     // letters
#define KS 3       // conv taps

// Single persistent kernel: 296 blocks x 768 threads, 2 CTA/SM (all resident).
#define WPB 24
#define NTHREADS 768
#define B0 118
#define B1 118
#define B2 60
#define NBLOCKS (B0 + B1 + B2)          // 296 = 2 * 148
#define SMEM_BYTES (KS * NL * 128 * 2)  // 96 KB (encode table; reused in phase 1)

// Phase-1 split
#define PBLK 80     // blocks 0..79: P build (4 channels each = 320)
#define PACK0 80    // blocks 80..101: pack (22 * 768 = 16896 >= 16384)
#define PACK1 102

// Phase-1 P smem layout (within the 96 KB): emb half-tile + w rows
#define ES_STRIDE 156   // floats; 39 quads/row, gcd(39,8)=1 -> conflict-free
#define T0LEN 152       // first i-tile
#define T1LEN 148       // second i-tile

// Device scratch
__device__ __half g_Ph[KS][NL][DP];  // per-letter conv partials (bias in k=1 tap)
__device__ uint4  g_wpk[NW];         // packed letters: 16 u8 per word

// Grid barrier state (multi-launch safe: epoch read-before-arrive; graph
// replays are serialized so epoch is stable at kernel entry).
__device__ volatile unsigned g_epoch = 0;
__device__ unsigned g_cnt = 0;

// packed-f32x2 FMA (FFMA2) — PTX only
__device__ __forceinline__ void fma2(unsigned long long& d,
                                     unsigned long long a, unsigned long long b) {
    asm("fma.rn.f32x2 %0, %1, %2, %0;" : "+l"(d) : "l"(a), "l"(b));
}
__device__ __forceinline__ float2 unpack2(unsigned long long x) {
    float2 f;
    asm("mov.b64 {%0, %1}, %2;" : "=f"(f.x), "=f"(f.y) : "l"(x));
    return f;
}

#define GETL(l) ((lw[(l) >> 2] >> (((l) & 3) * 8)) & 0xFF)

#define INNER_BODY(loidx)                                                        \
    half2 m0 = NEGI, m1 = NEGI, m2 = NEGI, m3 = NEGI;                            \
    _Pragma("unroll")                                                            \
    for (int l = 0; l < WL; ++l) {                                               \
        uint4 a = Pv[(NL + GETL(l)) * 16 + (loidx)];                             \
        half2 h0 = *(half2*)&a.x, h1 = *(half2*)&a.y;                            \
        half2 h2 = *(half2*)&a.z, h3 = *(half2*)&a.w;                            \
        if (l > 0) {                                                             \
            uint4 q = Pv[GETL(l - 1) * 16 + (loidx)];                            \
            h0 = __hadd2(h0, *(half2*)&q.x); h1 = __hadd2(h1, *(half2*)&q.y);    \
            h2 = __hadd2(h2, *(half2*)&q.z); h3 = __hadd2(h3, *(half2*)&q.w);    \
        }                                                                        \
        if (l < WL - 1) {                                                        \
            uint4 q = Pv[(2 * NL + GETL(l + 1)) * 16 + (loidx)];                 \
            h0 = __hadd2(h0, *(half2*)&q.x); h1 = __hadd2(h1, *(half2*)&q.y);    \
            h2 = __hadd2(h2, *(half2*)&q.z); h3 = __hadd2(h3, *(half2*)&q.w);    \
        }                                                                        \
        m0 = __hmax2(m0, h0); m1 = __hmax2(m1, h1);                              \
        m2 = __hmax2(m2, h2); m3 = __hmax2(m3, h3);                              \
    }

__global__ __launch_bounds__(NTHREADS, 2) void fused_kernel(const int* __restrict__ words,
                                                            const float* __restrict__ emb,
                                                            const float* __restrict__ w,
                                                            const float* __restrict__ bias,
                                                            float* __restrict__ out) {
    extern __shared__ uint4 Pv[];  // 96 KB; phase 1 reuses it as float scratch
    const int b   = blockIdx.x;
    const int tid = threadIdx.x;

    // ======================= PHASE 1 =======================
    if (b < PBLK) {
        // ---- P build: 4 output channels, emb staged in 2 half-tiles ----
        float* es = (float*)Pv;                 // [128][ES_STRIDE]
        float* ws = es + NL * ES_STRIDE;        // [4][KS][304]

        const int ob = b * 4;
        const int j  = tid >> 7;                // 0..5; only 0..3 compute
        const int v  = tid & 127;
        const int o  = ob + j;

        // Stage w rows de-interleaved: ws[jj][k][i]
        for (int t = tid; t < 4 * D * KS; t += NTHREADS) {
            int jj = t / (D * KS), r = t % (D * KS);
            int oo = ob + jj;
            ws[(jj * KS + r % 3) * 304 + r / 3] = (oo < D) ? w[oo * D * KS + r] : 0.f;
        }

        typedef unsigned long long u64;
        u64 a0l = 0, a0h = 0, a1l = 0, a1h = 0, a2l = 0, a2h = 0;
        const int tstart[2] = {0, T0LEN};
        const int tlen[2]   = {T0LEN, T1LEN};
#pragma unroll
        for (int t = 0; t < 2; ++t) {
            const int i0 = tstart[t], L = tlen[t];
            __syncthreads();
            // stage emb[:, i0:i0+L] (float4 coalesced; L % 4 == 0)
            for (int idx = tid; idx < NL * (L / 4); idx += NTHREADS) {
                int vv = idx / (L / 4), c = idx % (L / 4);
                float4 val = *(const float4*)(emb + vv * D + i0 + c * 4);
                *(float4*)&es[vv * ES_STRIDE + c * 4] = val;
            }
            __syncthreads();
            if (j < 4) {
                const float* ev  = es + v * ES_STRIDE;
                const float* w0p = ws + (j * KS + 0) * 304 + i0;
                const float* w1p = ws + (j * KS + 1) * 304 + i0;
                const float* w2p = ws + (j * KS + 2) * 304 + i0;
#pragma unroll 4
                for (int i = 0; i < L; i += 4) {
                    ulonglong2 e2 = *(const ulonglong2*)(ev + i);
                    ulonglong2 w0 = *(const ulonglong2*)(w0p + i);
                    ulonglong2 w1 = *(const ulonglong2*)(w1p + i);
                    ulonglong2 w2 = *(const ulonglong2*)(w2p + i);
                    fma2(a0l, e2.x, w0.x); fma2(a0h, e2.y, w0.y);
                    fma2(a1l, e2.x, w1.x); fma2(a1h, e2.y, w1.y);
                    fma2(a2l, e2.x, w2.x); fma2(a2h, e2.y, w2.y);
                }
            }
        }
        if (j < 4) {
            float2 p0 = unpack2(a0l), q0 = unpack2(a0h);
            float2 p1 = unpack2(a1l), q1 = unpack2(a1h);
            float2 p2 = unpack2(a2l), q2 = unpack2(a2h);
            float a0 = (p0.x + p0.y) + (q0.x + q0.y);
            float a1 = (p1.x + p1.y) + (q1.x + q1.y);
            float a2 = (p2.x + p2.y) + (q2.x + q2.y);
            bool real = (o < D);
            float bv = real ? bias[o] : 0.f;
            g_Ph[0][v][o] = __float2half(real ? a0 : 0.f);
            g_Ph[1][v][o] = __float2half(real ? (a1 + bv) : 0.f);  // bias in k=1
            g_Ph[2][v][o] = __float2half(real ? a2 : 0.f);
        }
    } else if (b < PACK1) {
        // ---- pack words ----
        const int n = (b - PACK0) * NTHREADS + tid;
        if (n < NW) {
            unsigned r0 = 0, r1 = 0, r2 = 0, r3 = 0;
#pragma unroll
            for (int l = 0; l < 4; ++l)  r0 |= ((unsigned)words[l * NW + n] & 0xFF) << (l * 8);
#pragma unroll
            for (int l = 4; l < 8; ++l)  r1 |= ((unsigned)words[l * NW + n] & 0xFF) << ((l - 4) * 8);
#pragma unroll
            for (int l = 8; l < 12; ++l) r2 |= ((unsigned)words[l * NW + n] & 0xFF) << ((l - 8) * 8);
#pragma unroll
            for (int l = 12; l < 16; ++l) r3 |= ((unsigned)words[l * NW + n] & 0xFF) << ((l - 12) * 8);
            g_wpk[n] = make_uint4(r0, r1, r2, r3);
        }
    }
    // blocks >= PACK1: nothing in phase 1

    // ======================= GRID BARRIER =======================
    __syncthreads();  // all block threads' phase-1 work done
    if (tid == 0) {
        unsigned e0 = g_epoch;            // read sense BEFORE arriving
        __threadfence();                  // publish this block's global writes
        unsigned old = atomicAdd(&g_cnt, 1);
        if (old == NBLOCKS - 1) {
            g_cnt = 0;                    // reset for next graph replay
            __threadfence();
            g_epoch = e0 + 1;             // release
        } else {
            while (g_epoch == e0) { __nanosleep(64); }
        }
        __threadfence();                  // acquire
    }
    __syncthreads();

    // ======================= PHASE 2: ENCODE =======================
    int slice, lb, nb;
    if (b < B0)           { slice = 0; lb = b;           nb = B0; }
    else if (b < B0 + B1) { slice = 1; lb = b - B0;      nb = B1; }
    else                  { slice = 2; lb = b - B0 - B1; nb = B2; }
    const int c0 = slice * 128;
    const int nchunk = (slice == 2) ? 8 : 16;

    const uint4* gP = (const uint4*)g_Ph;  // row stride DP/8 = 40 uint4
    for (int idx = tid; idx < KS * NL * nchunk; idx += NTHREADS) {
        int r = idx / nchunk, c = idx % nchunk;
        Pv[r * 16 + c] = gP[r * (DP / 8) + slice * 16 + c];
    }
    __syncthreads();

    const int lane  = tid & 31;
    const int wid   = tid >> 5;
    const int wsl   = lb * WPB + wid;
    const int nwarp = nb * WPB;

    const __half NH = __ushort_as_half((unsigned short)0xFC00);  // -inf
    const half2 NEGI = __halves2half2(NH, NH);

    if (slice < 2) {
        // ---- 128-ch slice: 2 words per warp (16-lane halves) ----
        const int lo   = lane & 15;
        const int half = lane >> 4;
        const int ch   = c0 + lo * 8;

        uint4 pk = g_wpk[2 * wsl + half];
        for (int p = wsl; p < NW / 2; p += nwarp) {
            const int pn = p + nwarp;
            uint4 nxt = make_uint4(0, 0, 0, 0);
            if (pn < NW / 2) nxt = g_wpk[2 * pn + half];

            unsigned lw[4] = {pk.x, pk.y, pk.z, pk.w};
            const int gw = 2 * p + half;

            INNER_BODY(lo)

            float2 f0 = __half22float2(m0), f1 = __half22float2(m1);
            float2 f2 = __half22float2(m2), f3 = __half22float2(m3);
            float* op = out + (size_t)gw * D + ch;
            float4 r;
            r.x = fmaxf(f0.x, 0.f); r.y = fmaxf(f0.y, 0.f);
            r.z = fmaxf(f1.x, 0.f); r.w = fmaxf(f1.y, 0.f);
            *(float4*)op = r;
            r.x = fmaxf(f2.x, 0.f); r.y = fmaxf(f2.y, 0.f);
            r.z = fmaxf(f3.x, 0.f); r.w = fmaxf(f3.y, 0.f);
            *(float4*)(op + 4) = r;

            pk = nxt;
        }
    } else {
        // ---- 64-ch slice (channels 256..299 real): 4 words per warp ----
        const int lo8 = lane & 7;
        const int g   = lane >> 3;
        const int ch  = c0 + lo8 * 8;  // 256..312

        uint4 pk = g_wpk[4 * wsl + g];
        for (int p = wsl; p < NW / 4; p += nwarp) {
            const int pn = p + nwarp;
            uint4 nxt = make_uint4(0, 0, 0, 0);
            if (pn < NW / 4) nxt = g_wpk[4 * pn + g];

            unsigned lw[4] = {pk.x, pk.y, pk.z, pk.w};
            const int gw = 4 * p + g;

            INNER_BODY(lo8)

            float2 f0 = __half22float2(m0), f1 = __half22float2(m1);
            float2 f2 = __half22float2(m2), f3 = __half22float2(m3);
            float* op = out + (size_t)gw * D + ch;
            if (ch < D) {
                float4 r;
                r.x = fmaxf(f0.x, 0.f); r.y = fmaxf(f0.y, 0.f);
                r.z = fmaxf(f1.x, 0.f); r.w = fmaxf(f1.y, 0.f);
                *(float4*)op = r;
            }
            if (ch + 4 < D) {
                float4 r;
                r.x = fmaxf(f2.x, 0.f); r.y = fmaxf(f2.y, 0.f);
                r.z = fmaxf(f3.x, 0.f); r.w = fmaxf(f3.y, 0.f);
                *(float4*)(op + 4) = r;
            }
            pk = nxt;
        }
    }
}

// ---------------------------------------------------------------------------
// Launch. Inputs: words(int32), emb(f32), conv_w(f32), conv_b(f32). Out f32.
// ---------------------------------------------------------------------------
extern "C" void kernel_launch(void* const* d_in, const int* in_sizes, int n_in,
                              void* d_out, int out_size) {
    const int*   words = (const int*)d_in[0];
    const float* emb   = (const float*)d_in[1];
    const float* w     = (const float*)d_in[2];
    const float* b     = (const float*)d_in[3];
    float*       out   = (float*)d_out;

    cudaFuncSetAttribute(fused_kernel,
                         cudaFuncAttributeMaxDynamicSharedMemorySize, SMEM_BYTES);
    fused_kernel<<<NBLOCKS, NTHREADS, SMEM_BYTES>>>(words, emb, w, b, out);
}